// round 7
// baseline (speedup 1.0000x reference)
#include <cuda_runtime.h>
#include <cuda_fp16.h>
#include <cstdint>

// ---------------------------------------------------------------------------
// Fused persistent LSTM classifier, v6: windowed pipelining.
// R4 loop bodies + math (447us baseline), new sync topology:
//  - h0 lives in an 8-slot ring; L1 runs one 4-step WINDOW behind L0.
//  - __syncthreads() only at window boundaries (every 4 steps).
//  - inside a window: each group orders its own warps with ONE private
//    named barrier per step (L0: id1/256, L1: id2/256). No cross-group
//    sync inside a window; ring halves are disjoint by construction.
//  - x: 8-slot ring, committed one window ahead by L0 (owner of x pipe).
// ---------------------------------------------------------------------------

namespace {

constexpr int T_ = 512, I_ = 128, H_ = 64, E_ = 128, C_ = 100;
constexpr int BT = 8, NCTA = 128, NTHR = 512;
constexpr int WIN = 4, NWIN = T_ / WIN;          // 128 windows

constexpr int SWI = 136;
constexpr int SWH = 72;
constexpr int SXS = 136;
constexpr int SHS = 72;
constexpr int XROW = BT * SXS;                   // halves per x slot
constexpr int HROW = BT * SHS;                   // halves per h slot

constexpr int OFF_WIH0 = 0;                      // 69632
constexpr int OFF_WHH0 = 69632;                  // 36864
constexpr int OFF_WIH1 = 106496;
constexpr int OFF_WHH1 = 143360;
constexpr int OFF_B0   = 180224;
constexpr int OFF_B1   = 181248;
constexpr int OFF_X    = 182272;                 // 8 slots * 2176B = 17408
constexpr int OFF_H0   = 199680;                 // 8 slots * 1152B = 9216
constexpr int OFF_H1   = 208896;                 // 2 slots * 1152B = 2304
constexpr int OFF_HF   = 211200;                 // 2048
constexpr int OFF_E    = 213248;                 // 4096
constexpr int OFF_F    = 217344;                 // 4096
constexpr int SMEM_TOTAL = 221440;

__device__ __forceinline__ void bar_sync(int id, int cnt) {
    asm volatile("bar.sync %0, %1;" :: "r"(id), "r"(cnt) : "memory");
}

__device__ __forceinline__ float tanh_ap(float x) {
    float y;
    asm("tanh.approx.f32 %0, %1;" : "=f"(y) : "f"(x));
    return y;
}
__device__ __forceinline__ float fsig(float x) {
    return fmaf(0.5f, tanh_ap(0.5f * x), 0.5f);
}

__device__ __forceinline__ void mma4(float c[4], const uint32_t a[4],
                                     uint32_t b0, uint32_t b1) {
    asm volatile(
        "mma.sync.aligned.m16n8k16.row.col.f32.f16.f16.f32 "
        "{%0,%1,%2,%3},{%4,%5,%6,%7},{%8,%9},{%0,%1,%2,%3};\n"
        : "+f"(c[0]), "+f"(c[1]), "+f"(c[2]), "+f"(c[3])
        : "r"(a[0]), "r"(a[1]), "r"(a[2]), "r"(a[3]), "r"(b0), "r"(b1));
}

template <int KT, int S>
__device__ __forceinline__ void load_w(const half* __restrict__ sW, int wc, int g,
                                       int t, uint32_t f[KT][2][4]) {
#pragma unroll
    for (int kt = 0; kt < KT; kt++)
#pragma unroll
        for (int u = 0; u < 2; u++) {
            const half* p = sW + (wc * 32 + u * 16 + g) * S + kt * 16 + 2 * t;
            f[kt][u][0] = *(const uint32_t*)(p);
            f[kt][u][1] = *(const uint32_t*)(p + 8 * S);
            f[kt][u][2] = *(const uint32_t*)(p + 8);
            f[kt][u][3] = *(const uint32_t*)(p + 8 * S + 8);
        }
}

__device__ __forceinline__ void acc_set(float a[2][4], const float b[2][2]) {
#pragma unroll
    for (int u = 0; u < 2; u++) {
        a[u][0] = b[u][0]; a[u][1] = b[u][0];
        a[u][2] = b[u][1]; a[u][3] = b[u][1];
    }
}

__global__ void __launch_bounds__(NTHR, 1)
lstm_fused(const float* __restrict__ x,
           const float* __restrict__ Wih0, const float* __restrict__ Whh0,
           const float* __restrict__ bih0, const float* __restrict__ bhh0,
           const float* __restrict__ Wih1, const float* __restrict__ Whh1,
           const float* __restrict__ bih1, const float* __restrict__ bhh1,
           const float* __restrict__ Wproj, const float* __restrict__ bproj,
           const float* __restrict__ Wfc1, const float* __restrict__ bfc1,
           const float* __restrict__ Wfc2, const float* __restrict__ bfc2,
           float* __restrict__ out)
{
    extern __shared__ unsigned char smem[];
    half*  sWih0 = (half*)(smem + OFF_WIH0);
    half*  sWhh0 = (half*)(smem + OFF_WHH0);
    half*  sWih1 = (half*)(smem + OFF_WIH1);
    half*  sWhh1 = (half*)(smem + OFF_WHH1);
    float* sB0   = (float*)(smem + OFF_B0);
    float* sB1   = (float*)(smem + OFF_B1);
    half*  sX    = (half*)(smem + OFF_X);
    half*  sH0   = (half*)(smem + OFF_H0);
    half*  sH1   = (half*)(smem + OFF_H1);
    float* sHF   = (float*)(smem + OFF_HF);
    float* sE    = (float*)(smem + OFF_E);
    float* sF    = (float*)(smem + OFF_F);

    const int tid  = threadIdx.x;
    const int lane = tid & 31;
    const int w    = tid >> 5;
    const int wc   = w & 7;
    const int g    = lane >> 2;
    const int t    = lane & 3;
    const int b0r  = blockIdx.x * BT;

    // ---- stage permuted fp16 weights + fused biases ----
    for (int i = tid; i < 256 * 128; i += NTHR) {
        int p = i >> 7, k = i & 127;
        int m = (((p >> 4) & 1) * 2 + ((p >> 3) & 1)) * 64 + (p >> 5) * 8 + (p & 7);
        sWih0[p * SWI + k] = __float2half(Wih0[m * 128 + k]);
    }
    for (int i = tid; i < 256 * 64; i += NTHR) {
        int p = i >> 6, k = i & 63;
        int m = (((p >> 4) & 1) * 2 + ((p >> 3) & 1)) * 64 + (p >> 5) * 8 + (p & 7);
        sWhh0[p * SWH + k] = __float2half(Whh0[m * 64 + k]);
        sWih1[p * SWH + k] = __float2half(Wih1[m * 64 + k]);
        sWhh1[p * SWH + k] = __float2half(Whh1[m * 64 + k]);
    }
    for (int i = tid; i < 256; i += NTHR) {
        sB0[i] = bih0[i] + bhh0[i];
        sB1[i] = bih1[i] + bhh1[i];
    }
    // zero all h0 slots (slot 7 doubles as h0(-1)=0) and both h1 slots
    for (int i = tid; i < 8 * HROW; i += NTHR) sH0[i] = __float2half(0.f);
    for (int i = tid; i < 2 * HROW; i += NTHR) sH1[i] = __float2half(0.f);

    const int n0 = 2 * t;
    const int j  = wc * 8 + g;

    // x prologue: L0 warps fill slots 0..3 with x(0..3), xpre = x(4)
    const int xr = wc, xi = lane * 4;
    const float* xrow = x + ((size_t)(b0r + xr) * T_) * I_ + xi;
    float4 xpre = make_float4(0.f, 0.f, 0.f, 0.f);
    if (w < 8) {
#pragma unroll
        for (int s = 0; s < 4; s++) {
            float4 xv = *(const float4*)(xrow + (size_t)s * I_);
            half* xw = sX + s * XROW;
            *(half2*)(xw + xr * SXS + xi)     = __floats2half2_rn(xv.x, xv.y);
            *(half2*)(xw + xr * SXS + xi + 2) = __floats2half2_rn(xv.z, xv.w);
        }
        xpre = *(const float4*)(xrow + 4 * (size_t)I_);
    }
    __syncthreads();

    if (w < 8) {
        // =============== layer-0 group: steps 4win .. 4win+3 ===============
        uint32_t fih0[8][2][4], fhh0[4][2][4];
        load_w<8, SWI>(sWih0, wc, g, t, fih0);
        load_w<4, SWH>(sWhh0, wc, g, t, fhh0);
        float bb0[2][2];
#pragma unroll
        for (int u = 0; u < 2; u++)
#pragma unroll
            for (int v = 0; v < 2; v++)
                bb0[u][v] = sB0[(2 * u + v) * 64 + wc * 8 + g];
        float c00 = 0.f, c01 = 0.f;

        for (int win = 0; win < NWIN + 1; win++) {
            if (win < NWIN) {
#pragma unroll
                for (int i = 0; i < WIN; i++) {
                    const int k  = win * WIN + i;
                    const int sk = k & 7, skp = (k - 1) & 7;   // k=0 -> slot 7 (zeros)
                    float a[2][4];
                    acc_set(a, bb0);
                    const half* H0r = sH0 + skp * HROW;
#pragma unroll
                    for (int kt = 0; kt < 4; kt++) {
                        const half* q = H0r + g * SHS + kt * 16 + 2 * t;
                        uint32_t b0 = *(const uint32_t*)(q);
                        uint32_t b1 = *(const uint32_t*)(q + 8);
                        mma4(a[0], fhh0[kt][0], b0, b1);
                        mma4(a[1], fhh0[kt][1], b0, b1);
                    }
                    const half* X = sX + sk * XROW;
#pragma unroll
                    for (int kt = 0; kt < 8; kt++) {
                        const half* q = X + g * SXS + kt * 16 + 2 * t;
                        uint32_t b0 = *(const uint32_t*)(q);
                        uint32_t b1 = *(const uint32_t*)(q + 8);
                        mma4(a[0], fih0[kt][0], b0, b1);
                        mma4(a[1], fih0[kt][1], b0, b1);
                    }
                    {   // x pipeline: commit x(k+4) -> slot (k+4)&7, fetch x(k+5)
                        half* xw = sX + ((k + 4) & 7) * XROW;
                        *(half2*)(xw + xr * SXS + xi)     = __floats2half2_rn(xpre.x, xpre.y);
                        *(half2*)(xw + xr * SXS + xi + 2) = __floats2half2_rn(xpre.z, xpre.w);
                        int tn = k + 5; if (tn > T_ - 1) tn = T_ - 1;
                        xpre = *(const float4*)(xrow + (size_t)tn * I_);
                    }
                    // L0 cell -> h0(k) into slot sk
                    float i0 = fsig(a[0][0]), i1 = fsig(a[0][1]);
                    float f0 = fsig(a[0][2]), f1 = fsig(a[0][3]);
                    float g0 = tanh_ap(a[1][0]), g1 = tanh_ap(a[1][1]);
                    float o0 = fsig(a[1][2]), o1 = fsig(a[1][3]);
                    c00 = f0 * c00 + i0 * g0;
                    c01 = f1 * c01 + i1 * g1;
                    half* h0w = sH0 + sk * HROW;
                    h0w[n0 * SHS + j]       = __float2half(o0 * tanh_ap(c00));
                    h0w[(n0 + 1) * SHS + j] = __float2half(o1 * tanh_ap(c01));
                    bar_sync(1, 256);       // L0 group: h0(k) visible to L0 warps
                }
            }
            __syncthreads();                // window boundary (both groups)
        }
    } else {
        // =============== layer-1 group: steps 4(win-1) .. 4(win-1)+3 ===============
        uint32_t fih1[4][2][4], fhh1[4][2][4];
        load_w<4, SWH>(sWih1, wc, g, t, fih1);
        load_w<4, SWH>(sWhh1, wc, g, t, fhh1);
        float bb1[2][2];
#pragma unroll
        for (int u = 0; u < 2; u++)
#pragma unroll
            for (int v = 0; v < 2; v++)
                bb1[u][v] = sB1[(2 * u + v) * 64 + wc * 8 + g];
        float c10 = 0.f, c11 = 0.f;

        for (int win = 0; win < NWIN + 1; win++) {
            if (win >= 1) {
#pragma unroll
                for (int i = 0; i < WIN; i++) {
                    const int m = (win - 1) * WIN + i;
                    float a[2][4];
                    acc_set(a, bb1);
                    const half* H0r = sH0 + (m & 7) * HROW;
                    const half* H1r = sH1 + ((m & 1) ^ 1) * HROW;
#pragma unroll
                    for (int kt = 0; kt < 4; kt++) {
                        const half* q0 = H0r + g * SHS + kt * 16 + 2 * t;
                        uint32_t b0 = *(const uint32_t*)(q0);
                        uint32_t b1 = *(const uint32_t*)(q0 + 8);
                        mma4(a[0], fih1[kt][0], b0, b1);
                        mma4(a[1], fih1[kt][1], b0, b1);
                        const half* q1 = H1r + g * SHS + kt * 16 + 2 * t;
                        uint32_t d0 = *(const uint32_t*)(q1);
                        uint32_t d1 = *(const uint32_t*)(q1 + 8);
                        mma4(a[0], fhh1[kt][0], d0, d1);
                        mma4(a[1], fhh1[kt][1], d0, d1);
                    }
                    float i0 = fsig(a[0][0]), i1 = fsig(a[0][1]);
                    float f0 = fsig(a[0][2]), f1 = fsig(a[0][3]);
                    float g0 = tanh_ap(a[1][0]), g1 = tanh_ap(a[1][1]);
                    float o0 = fsig(a[1][2]), o1 = fsig(a[1][3]);
                    c10 = f0 * c10 + i0 * g0;
                    c11 = f1 * c11 + i1 * g1;
                    float h0v = o0 * tanh_ap(c10), h1v = o1 * tanh_ap(c11);
                    half* h1w = sH1 + (m & 1) * HROW;
                    h1w[n0 * SHS + j]       = __float2half(h0v);
                    h1w[(n0 + 1) * SHS + j] = __float2half(h1v);
                    if (m == T_ - 1) {
                        sHF[n0 * H_ + j]       = h0v;
                        sHF[(n0 + 1) * H_ + j] = h1v;
                    }
                    bar_sync(2, 256);       // L1 group: h1(m) visible to L1 warps
                }
            }
            __syncthreads();                // window boundary (both groups)
        }
    }

    __syncthreads();    // join before head (sHF complete)

    // ---- head: proj -> relu -> fc1 -> relu -> fc2 ----
#pragma unroll
    for (int q = 0; q < 2; q++) {
        int idx = tid + q * NTHR;
        int r = idx >> 7, e = idx & 127;
        float a = bproj[e];
        const float* wp = Wproj + e * H_;
        const float* hp = sHF + r * H_;
#pragma unroll 8
        for (int kk = 0; kk < H_; kk++) a += hp[kk] * wp[kk];
        sE[r * E_ + e] = fmaxf(a, 0.f);
    }
    __syncthreads();
#pragma unroll
    for (int q = 0; q < 2; q++) {
        int idx = tid + q * NTHR;
        int r = idx >> 7, e = idx & 127;
        float a = bfc1[e];
        const float* wp = Wfc1 + e * E_;
        const float* hp = sE + r * E_;
#pragma unroll 8
        for (int kk = 0; kk < E_; kk++) a += hp[kk] * wp[kk];
        sF[r * E_ + e] = fmaxf(a, 0.f);
    }
    __syncthreads();
    for (int idx = tid; idx < BT * C_; idx += NTHR) {
        int r = idx / C_, c = idx - r * C_;
        float a = bfc2[c];
        const float* wp = Wfc2 + c * E_;
        const float* hp = sF + r * E_;
#pragma unroll 8
        for (int kk = 0; kk < E_; kk++) a += hp[kk] * wp[kk];
        out[(size_t)(b0r + r) * C_ + c] = a;
    }
}

}  // namespace

extern "C" void kernel_launch(void* const* d_in, const int* in_sizes, int n_in,
                              void* d_out, int out_size) {
    cudaFuncSetAttribute(lstm_fused, cudaFuncAttributeMaxDynamicSharedMemorySize,
                         SMEM_TOTAL);
    lstm_fused<<<NCTA, NTHR, SMEM_TOTAL>>>(
        (const float*)d_in[0],
        (const float*)d_in[1],  (const float*)d_in[2],
        (const float*)d_in[3],  (const float*)d_in[4],
        (const float*)d_in[5],  (const float*)d_in[6],
        (const float*)d_in[7],  (const float*)d_in[8],
        (const float*)d_in[9],  (const float*)d_in[10],
        (const float*)d_in[11], (const float*)d_in[12],
        (const float*)d_in[13], (const float*)d_in[14],
        (float*)d_out);
}

// round 8
// speedup vs baseline: 1.6489x; 1.6489x over previous
#include <cuda_runtime.h>
#include <cuda_fp16.h>
#include <cstdint>

// ---------------------------------------------------------------------------
// Fused persistent LSTM classifier, v7: functional 3-way specialization
// under the proven single global-barrier lockstep (one bar.sync 0 / step).
//  A (w 0-7):  feed-forward mma only -> f16 rings:
//              XGI0(k+2) = b0 + Wih0 @ x(k+2)   (ring0, depth 2)
//              G1I(k)    = b1 + Wih1 @ h0(k)    (ring1, depth 2)
//  B (w 8-11): L0 recurrence: Whh0 @ h0(k) + ring0 -> cell -> h0(k+1)
//  C (w12-15): L1 recurrence retimed +1 step: Whh1 @ h1(k-2) + ring1(k-1)
//              -> cell -> h1(k-1); epilogue computes h1(511).
//  x prefetch: split across B+C warps (1 batch row each), 2-step LDG slack.
//  All weight fragments register-resident. Biases travel inside the rings.
// ---------------------------------------------------------------------------

namespace {

constexpr int T_ = 512, I_ = 128, H_ = 64, E_ = 128, C_ = 100;
constexpr int BT = 8, NCTA = 128, NTHR = 512;

constexpr int SWI = 136;           // W_ih0 row stride (halves)
constexpr int SWH = 72;            // K=64 weight row stride
constexpr int SXS = 136;           // x tile row stride
constexpr int SHS = 72;            // h tile row stride
constexpr int XROW = BT * SXS;     // halves per x slot (1088)
constexpr int HROW = BT * SHS;     // halves per h slot (576)
constexpr int RSLOT = 2048;        // halves per ring slot (256 gates * 8 batch)

constexpr int OFF_WIH0 = 0;        // 69632
constexpr int OFF_WHH0 = 69632;    // 36864
constexpr int OFF_WIH1 = 106496;   // 36864
constexpr int OFF_WHH1 = 143360;   // 36864
constexpr int OFF_B0   = 180224;   // 1024
constexpr int OFF_B1   = 181248;   // 1024
constexpr int OFF_X    = 182272;   // 4 slots * 2176 = 8704
constexpr int OFF_H0   = 190976;   // 2 slots * 1152 = 2304
constexpr int OFF_H1   = 193280;   // 2304
constexpr int OFF_R0   = 195584;   // 2 slots * 4096 = 8192
constexpr int OFF_R1   = 203776;   // 8192
constexpr int OFF_HF   = 211968;   // 2048
constexpr int OFF_E    = 214016;   // 4096
constexpr int OFF_F    = 218112;   // 4096
constexpr int SMEM_TOTAL = 222208;

#define BARRIER() asm volatile("bar.sync 0;" ::: "memory")

__device__ __forceinline__ float tanh_ap(float x) {
    float y;
    asm("tanh.approx.f32 %0, %1;" : "=f"(y) : "f"(x));
    return y;
}
__device__ __forceinline__ float fsig(float x) {
    return fmaf(0.5f, tanh_ap(0.5f * x), 0.5f);
}

__device__ __forceinline__ void mma4(float c[4], const uint32_t a[4],
                                     uint32_t b0, uint32_t b1) {
    asm volatile(
        "mma.sync.aligned.m16n8k16.row.col.f32.f16.f16.f32 "
        "{%0,%1,%2,%3},{%4,%5,%6,%7},{%8,%9},{%0,%1,%2,%3};\n"
        : "+f"(c[0]), "+f"(c[1]), "+f"(c[2]), "+f"(c[3])
        : "r"(a[0]), "r"(a[1]), "r"(a[2]), "r"(a[3]), "r"(b0), "r"(b1));
}

template <int KT, int S>
__device__ __forceinline__ void load_w(const half* __restrict__ sW, int wc, int g,
                                       int t, uint32_t f[KT][2][4]) {
#pragma unroll
    for (int kt = 0; kt < KT; kt++)
#pragma unroll
        for (int u = 0; u < 2; u++) {
            const half* p = sW + (wc * 32 + u * 16 + g) * S + kt * 16 + 2 * t;
            f[kt][u][0] = *(const uint32_t*)(p);
            f[kt][u][1] = *(const uint32_t*)(p + 8 * S);
            f[kt][u][2] = *(const uint32_t*)(p + 8);
            f[kt][u][3] = *(const uint32_t*)(p + 8 * S + 8);
        }
}

// A: bias(from smem) + W @ act  ->  packed f16 uint4 (ring entry)
template <int KT, int S>
__device__ __forceinline__ void a_gemm_pack(const half* __restrict__ Xb,
                                            const uint32_t f[][2][4],
                                            const float* __restrict__ bs,
                                            int jj, int g, int t,
                                            uint4* __restrict__ dst) {
    float a[2][4];
#pragma unroll
    for (int u = 0; u < 2; u++) {
        float v0 = bs[(2 * u) * 64 + jj];
        float v1 = bs[(2 * u + 1) * 64 + jj];
        a[u][0] = v0; a[u][1] = v0; a[u][2] = v1; a[u][3] = v1;
    }
#pragma unroll
    for (int kt = 0; kt < KT; kt++) {
        const half* q = Xb + g * S + kt * 16 + 2 * t;
        uint32_t b0 = *(const uint32_t*)(q);
        uint32_t b1 = *(const uint32_t*)(q + 8);
        mma4(a[0], f[kt][0], b0, b1);
        mma4(a[1], f[kt][1], b0, b1);
    }
    half2 h0 = __floats2half2_rn(a[0][0], a[0][1]);
    half2 h1 = __floats2half2_rn(a[0][2], a[0][3]);
    half2 h2 = __floats2half2_rn(a[1][0], a[1][1]);
    half2 h3 = __floats2half2_rn(a[1][2], a[1][3]);
    uint4 v;
    v.x = *(uint32_t*)&h0; v.y = *(uint32_t*)&h1;
    v.z = *(uint32_t*)&h2; v.w = *(uint32_t*)&h3;
    *dst = v;
}

// unpack ring entry and add own hh accumulator -> gate preacts
__device__ __forceinline__ void unpack_add(uint4 v, const float acc[2][4],
                                           float G[2][4]) {
    float2 p;
    p = __half22float2(*(const half2*)&v.x); G[0][0] = acc[0][0] + p.x; G[0][1] = acc[0][1] + p.y;
    p = __half22float2(*(const half2*)&v.y); G[0][2] = acc[0][2] + p.x; G[0][3] = acc[0][3] + p.y;
    p = __half22float2(*(const half2*)&v.z); G[1][0] = acc[1][0] + p.x; G[1][1] = acc[1][1] + p.y;
    p = __half22float2(*(const half2*)&v.w); G[1][2] = acc[1][2] + p.x; G[1][3] = acc[1][3] + p.y;
}

__device__ __forceinline__ void lstm_cell2(const float G[2][4], float& ca, float& cb,
                                           float& ha, float& hb) {
    float i0 = fsig(G[0][0]), i1 = fsig(G[0][1]);
    float f0 = fsig(G[0][2]), f1 = fsig(G[0][3]);
    float g0 = tanh_ap(G[1][0]), g1 = tanh_ap(G[1][1]);
    float o0 = fsig(G[1][2]), o1 = fsig(G[1][3]);
    ca = f0 * ca + i0 * g0;
    cb = f1 * cb + i1 * g1;
    ha = o0 * tanh_ap(ca);
    hb = o1 * tanh_ap(cb);
}

__global__ void __launch_bounds__(NTHR, 1)
lstm_fused(const float* __restrict__ x,
           const float* __restrict__ Wih0, const float* __restrict__ Whh0,
           const float* __restrict__ bih0, const float* __restrict__ bhh0,
           const float* __restrict__ Wih1, const float* __restrict__ Whh1,
           const float* __restrict__ bih1, const float* __restrict__ bhh1,
           const float* __restrict__ Wproj, const float* __restrict__ bproj,
           const float* __restrict__ Wfc1, const float* __restrict__ bfc1,
           const float* __restrict__ Wfc2, const float* __restrict__ bfc2,
           float* __restrict__ out)
{
    extern __shared__ unsigned char smem[];
    half*  sWih0 = (half*)(smem + OFF_WIH0);
    half*  sWhh0 = (half*)(smem + OFF_WHH0);
    half*  sWih1 = (half*)(smem + OFF_WIH1);
    half*  sWhh1 = (half*)(smem + OFF_WHH1);
    float* sB0   = (float*)(smem + OFF_B0);
    float* sB1   = (float*)(smem + OFF_B1);
    half*  sX    = (half*)(smem + OFF_X);
    half*  sH0   = (half*)(smem + OFF_H0);
    half*  sH1   = (half*)(smem + OFF_H1);
    half*  sR0   = (half*)(smem + OFF_R0);
    half*  sR1   = (half*)(smem + OFF_R1);
    float* sHF   = (float*)(smem + OFF_HF);
    float* sE    = (float*)(smem + OFF_E);
    float* sF    = (float*)(smem + OFF_F);

    const int tid  = threadIdx.x;
    const int lane = tid & 31;
    const int w    = tid >> 5;
    const int g    = lane >> 2;
    const int t    = lane & 3;
    const int b0r  = blockIdx.x * BT;
    const int n0   = 2 * t;

    // ---- stage permuted fp16 weights + fused biases + x(0..3) ----
    for (int i = tid; i < 256 * 128; i += NTHR) {
        int p = i >> 7, k = i & 127;
        int m = (((p >> 4) & 1) * 2 + ((p >> 3) & 1)) * 64 + (p >> 5) * 8 + (p & 7);
        sWih0[p * SWI + k] = __float2half(Wih0[m * 128 + k]);
    }
    for (int i = tid; i < 256 * 64; i += NTHR) {
        int p = i >> 6, k = i & 63;
        int m = (((p >> 4) & 1) * 2 + ((p >> 3) & 1)) * 64 + (p >> 5) * 8 + (p & 7);
        sWhh0[p * SWH + k] = __float2half(Whh0[m * 64 + k]);
        sWih1[p * SWH + k] = __float2half(Wih1[m * 64 + k]);
        sWhh1[p * SWH + k] = __float2half(Whh1[m * 64 + k]);
    }
    for (int i = tid; i < 256; i += NTHR) {
        sB0[i] = bih0[i] + bhh0[i];
        sB1[i] = bih1[i] + bhh1[i];
    }
    for (int i = tid; i < 2 * HROW; i += NTHR)
        sH1[i] = __float2half(0.f);                    // h1(-1) = h1(-2) = 0
    for (int i = tid; i < 4 * BT * 128; i += NTHR) {   // x(0..3) -> slots 0..3
        int s = i >> 10, rem = i & 1023;
        int r = rem >> 7, c = rem & 127;
        sX[s * XROW + r * SXS + c] =
            __float2half(x[((size_t)(b0r + r) * T_ + s) * I_ + c]);
    }
    __syncthreads();

    if (w < 8) {
        // =============== group A: feed-forward mma -> rings ===============
        const int wc = w, jj = wc * 8 + g;
        uint32_t fih0[8][2][4], fih1[4][2][4];
        load_w<8, SWI>(sWih0, wc, g, t, fih0);
        load_w<4, SWH>(sWih1, wc, g, t, fih1);
        uint4* r0me_0 = (uint4*)(sR0 + 0 * RSLOT + (wc * 32 + lane) * 8);
        uint4* r0me_1 = (uint4*)(sR0 + 1 * RSLOT + (wc * 32 + lane) * 8);
        uint4* r1me_0 = (uint4*)(sR1 + 0 * RSLOT + (wc * 32 + lane) * 8);
        uint4* r1me_1 = (uint4*)(sR1 + 1 * RSLOT + (wc * 32 + lane) * 8);

        // prologue: XGI0(0) -> ring0 slot 0
        a_gemm_pack<8, SXS>(sX, fih0, sB0, jj, g, t, r0me_0);
        BARRIER();
        // prologue: XGI0(1) -> ring0 slot 1 (B computes h0(0) meanwhile)
        a_gemm_pack<8, SXS>(sX + XROW, fih0, sB0, jj, g, t, r0me_1);
        BARRIER();

        for (int k = 0; k < T_; k++) {
            const int pk = k & 1;
            // XGI0(k+2) -> ring0 slot k&1
            a_gemm_pack<8, SXS>(sX + ((k + 2) & 3) * XROW, fih0, sB0, jj, g, t,
                                pk ? r0me_1 : r0me_0);
            // G1I(k) = b1 + Wih1 @ h0(k) -> ring1 slot k&1
            a_gemm_pack<4, SHS>(sH0 + pk * HROW, fih1, sB1, jj, g, t,
                                pk ? r1me_1 : r1me_0);
            BARRIER();
        }
    } else if (w < 12) {
        // =============== group B: layer-0 recurrence ===============
        const int d = w - 8;
        uint32_t fhh0[2][4][2][4];
        load_w<4, SWH>(sWhh0, 2 * d,     g, t, fhh0[0]);
        load_w<4, SWH>(sWhh0, 2 * d + 1, g, t, fhh0[1]);
        float c0[2][2] = {{0.f, 0.f}, {0.f, 0.f}};

        // x pipeline: row d
        const int xr = d, xi = lane * 4;
        const float* xrow = x + ((size_t)(b0r + xr) * T_) * I_ + xi;
        float4 xpA = *(const float4*)(xrow + 4 * (size_t)I_);   // x(4)
        float4 xpB = *(const float4*)(xrow + 5 * (size_t)I_);   // x(5)

        BARRIER();                                   // XGI0(0) ready
        // prologue: h0(0) = cell(XGI0(0)), no hh term
#pragma unroll
        for (int s = 0; s < 2; s++) {
            uint4 rv = *(const uint4*)(sR0 + ((2 * d + s) * 32 + lane) * 8);
            float z[2][4] = {{0.f, 0.f, 0.f, 0.f}, {0.f, 0.f, 0.f, 0.f}};
            float G[2][4];
            unpack_add(rv, z, G);
            float ha, hb;
            lstm_cell2(G, c0[s][0], c0[s][1], ha, hb);
            int js = (2 * d + s) * 8 + g;
            sH0[n0 * SHS + js]       = __float2half(ha);
            sH0[(n0 + 1) * SHS + js] = __float2half(hb);
        }
        BARRIER();

        for (int k = 0; k < T_; k++) {
            const int pk = k & 1;
            const half* H0r = sH0 + pk * HROW;
            uint32_t bh[4][2];
#pragma unroll
            for (int kt = 0; kt < 4; kt++) {
                const half* q = H0r + g * SHS + kt * 16 + 2 * t;
                bh[kt][0] = *(const uint32_t*)(q);
                bh[kt][1] = *(const uint32_t*)(q + 8);
            }
            float acc[2][2][4];
#pragma unroll
            for (int s = 0; s < 2; s++)
#pragma unroll
                for (int u = 0; u < 2; u++)
#pragma unroll
                    for (int e = 0; e < 4; e++) acc[s][u][e] = 0.f;
#pragma unroll
            for (int s = 0; s < 2; s++)
#pragma unroll
                for (int kt = 0; kt < 4; kt++) {
                    mma4(acc[s][0], fhh0[s][kt][0], bh[kt][0], bh[kt][1]);
                    mma4(acc[s][1], fhh0[s][kt][1], bh[kt][0], bh[kt][1]);
                }
            {   // x pipeline: STS x(k+4), LDG x(k+6)
                half* xw = sX + ((k + 4) & 3) * XROW;
                *(half2*)(xw + xr * SXS + xi)     = __floats2half2_rn(xpA.x, xpA.y);
                *(half2*)(xw + xr * SXS + xi + 2) = __floats2half2_rn(xpA.z, xpA.w);
                xpA = xpB;
                int tn = k + 6; if (tn > T_ - 1) tn = T_ - 1;
                xpB = *(const float4*)(xrow + (size_t)tn * I_);
            }
            half* h0w = sH0 + (1 - pk) * HROW;
#pragma unroll
            for (int s = 0; s < 2; s++) {
                uint4 rv = *(const uint4*)(sR0 + (1 - pk) * RSLOT +
                                           ((2 * d + s) * 32 + lane) * 8);
                float G[2][4];
                unpack_add(rv, acc[s], G);
                float ha, hb;
                lstm_cell2(G, c0[s][0], c0[s][1], ha, hb);
                int js = (2 * d + s) * 8 + g;
                h0w[n0 * SHS + js]       = __float2half(ha);
                h0w[(n0 + 1) * SHS + js] = __float2half(hb);
            }
            BARRIER();
        }
    } else {
        // =============== group C: layer-1 recurrence (retimed +1) ===============
        const int d = w - 12;
        uint32_t fhh1[2][4][2][4];
        load_w<4, SWH>(sWhh1, 2 * d,     g, t, fhh1[0]);
        load_w<4, SWH>(sWhh1, 2 * d + 1, g, t, fhh1[1]);
        float c1[2][2] = {{0.f, 0.f}, {0.f, 0.f}};

        // x pipeline: row 4+d
        const int xr = 4 + d, xi = lane * 4;
        const float* xrow = x + ((size_t)(b0r + xr) * T_) * I_ + xi;
        float4 xpA = *(const float4*)(xrow + 4 * (size_t)I_);
        float4 xpB = *(const float4*)(xrow + 5 * (size_t)I_);

        BARRIER();
        BARRIER();

        for (int k = 0; k < T_; k++) {
            const int pk = k & 1;
            {   // x pipeline
                half* xw = sX + ((k + 4) & 3) * XROW;
                *(half2*)(xw + xr * SXS + xi)     = __floats2half2_rn(xpA.x, xpA.y);
                *(half2*)(xw + xr * SXS + xi + 2) = __floats2half2_rn(xpA.z, xpA.w);
                xpA = xpB;
                int tn = k + 6; if (tn > T_ - 1) tn = T_ - 1;
                xpB = *(const float4*)(xrow + (size_t)tn * I_);
            }
            if (k >= 1) {
                // h1(k-1) = cell( G1I(k-1) + Whh1 @ h1(k-2) )
                const half* H1r = sH1 + pk * HROW;       // h1(k-2): slot k&1
                uint32_t bh[4][2];
#pragma unroll
                for (int kt = 0; kt < 4; kt++) {
                    const half* q = H1r + g * SHS + kt * 16 + 2 * t;
                    bh[kt][0] = *(const uint32_t*)(q);
                    bh[kt][1] = *(const uint32_t*)(q + 8);
                }
                float acc[2][2][4];
#pragma unroll
                for (int s = 0; s < 2; s++)
#pragma unroll
                    for (int u = 0; u < 2; u++)
#pragma unroll
                        for (int e = 0; e < 4; e++) acc[s][u][e] = 0.f;
#pragma unroll
                for (int s = 0; s < 2; s++)
#pragma unroll
                    for (int kt = 0; kt < 4; kt++) {
                        mma4(acc[s][0], fhh1[s][kt][0], bh[kt][0], bh[kt][1]);
                        mma4(acc[s][1], fhh1[s][kt][1], bh[kt][0], bh[kt][1]);
                    }
                half* h1w = sH1 + (1 - pk) * HROW;        // h1(k-1): slot (k-1)&1
#pragma unroll
                for (int s = 0; s < 2; s++) {
                    uint4 rv = *(const uint4*)(sR1 + (1 - pk) * RSLOT +
                                               ((2 * d + s) * 32 + lane) * 8);
                    float G[2][4];
                    unpack_add(rv, acc[s], G);
                    float ha, hb;
                    lstm_cell2(G, c1[s][0], c1[s][1], ha, hb);
                    int js = (2 * d + s) * 8 + g;
                    h1w[n0 * SHS + js]       = __float2half(ha);
                    h1w[(n0 + 1) * SHS + js] = __float2half(hb);
                }
            }
            BARRIER();
        }

        // epilogue: h1(511) = cell( G1I(511) + Whh1 @ h1(510) ) -> sHF (f32)
        {
            const half* H1r = sH1;                       // h1(510): slot 0
            uint32_t bh[4][2];
#pragma unroll
            for (int kt = 0; kt < 4; kt++) {
                const half* q = H1r + g * SHS + kt * 16 + 2 * t;
                bh[kt][0] = *(const uint32_t*)(q);
                bh[kt][1] = *(const uint32_t*)(q + 8);
            }
            float acc[2][2][4];
#pragma unroll
            for (int s = 0; s < 2; s++)
#pragma unroll
                for (int u = 0; u < 2; u++)
#pragma unroll
                    for (int e = 0; e < 4; e++) acc[s][u][e] = 0.f;
#pragma unroll
            for (int s = 0; s < 2; s++)
#pragma unroll
                for (int kt = 0; kt < 4; kt++) {
                    mma4(acc[s][0], fhh1[s][kt][0], bh[kt][0], bh[kt][1]);
                    mma4(acc[s][1], fhh1[s][kt][1], bh[kt][0], bh[kt][1]);
                }
#pragma unroll
            for (int s = 0; s < 2; s++) {
                uint4 rv = *(const uint4*)(sR1 + 1 * RSLOT +
                                           ((2 * d + s) * 32 + lane) * 8);
                float G[2][4];
                unpack_add(rv, acc[s], G);
                float ha, hb;
                lstm_cell2(G, c1[s][0], c1[s][1], ha, hb);
                int js = (2 * d + s) * 8 + g;
                sHF[n0 * H_ + js]       = ha;
                sHF[(n0 + 1) * H_ + js] = hb;
            }
        }
    }

    __syncthreads();    // join: sHF complete before head

    // ---- head: proj -> relu -> fc1 -> relu -> fc2 ----
#pragma unroll
    for (int q = 0; q < 2; q++) {
        int idx = tid + q * NTHR;
        int r = idx >> 7, e = idx & 127;
        float a = bproj[e];
        const float* wp = Wproj + e * H_;
        const float* hp = sHF + r * H_;
#pragma unroll 8
        for (int kk = 0; kk < H_; kk++) a += hp[kk] * wp[kk];
        sE[r * E_ + e] = fmaxf(a, 0.f);
    }
    __syncthreads();
#pragma unroll
    for (int q = 0; q < 2; q++) {
        int idx = tid + q * NTHR;
        int r = idx >> 7, e = idx & 127;
        float a = bfc1[e];
        const float* wp = Wfc1 + e * E_;
        const float* hp = sE + r * E_;
#pragma unroll 8
        for (int kk = 0; kk < E_; kk++) a += hp[kk] * wp[kk];
        sF[r * E_ + e] = fmaxf(a, 0.f);
    }
    __syncthreads();
    for (int idx = tid; idx < BT * C_; idx += NTHR) {
        int r = idx / C_, c = idx - r * C_;
        float a = bfc2[c];
        const float* wp = Wfc2 + c * E_;
        const float* hp = sF + r * E_;
#pragma unroll 8
        for (int kk = 0; kk < E_; kk++) a += hp[kk] * wp[kk];
        out[(size_t)(b0r + r) * C_ + c] = a;
    }
}

}  // namespace

extern "C" void kernel_launch(void* const* d_in, const int* in_sizes, int n_in,
                              void* d_out, int out_size) {
    cudaFuncSetAttribute(lstm_fused, cudaFuncAttributeMaxDynamicSharedMemorySize,
                         SMEM_TOTAL);
    lstm_fused<<<NCTA, NTHR, SMEM_TOTAL>>>(
        (const float*)d_in[0],
        (const float*)d_in[1],  (const float*)d_in[2],
        (const float*)d_in[3],  (const float*)d_in[4],
        (const float*)d_in[5],  (const float*)d_in[6],
        (const float*)d_in[7],  (const float*)d_in[8],
        (const float*)d_in[9],  (const float*)d_in[10],
        (const float*)d_in[11], (const float*)d_in[12],
        (const float*)d_in[13], (const float*)d_in[14],
        (float*)d_out);
}